// round 5
// baseline (speedup 1.0000x reference)
#include <cuda_runtime.h>
#include <cstdint>
#include <math.h>

// Problem constants
#define Bn   8
#define Hh   56
#define Ww   56
#define Cc   512
#define C2   256
#define HW   3136
#define BHW  25088
#define NHh  8

// ===========================================================================
// Scratch
// ===========================================================================
__device__ float g_xn   [BHW * Cc];
__device__ float g_xen  [BHW * Cc];
__device__ float g_bfeat[BHW * Cc];
__device__ float g_kv   [BHW * Cc];
__device__ float g_xcat [BHW * Cc];
__device__ float g_cut  [BHW * C2];
__device__ float g_e1   [BHW * C2];
__device__ float g_e2   [BHW * C2];
__device__ float g_pool [Bn * 49 * 1024];
__device__ float g_m    [Bn * 49 * C2];
__device__ float g_a49p [4 * 64 * 49 * 32];
__device__ float g_mpart[4 * 64 * 49];
__device__ float g_spart[4 * 64 * 49];
__device__ float g_a49  [64 * 49 * 32];
__device__ float g_wt   [1376256];         // tf32-rounded weights

#define WT_QCUT  0
#define WT_L     131072
#define WT_KV    393216
#define WT_EFORE 655360
#define WT_EBACK 786432
#define WT_PROJ  851968
#define WT_PROJE 1114112

// ===========================================================================
// helpers
// ===========================================================================
__device__ __forceinline__ uint32_t f2tf32(float x) {
    uint32_t y;
    asm("cvt.rna.tf32.f32 %0, %1;" : "=r"(y) : "f"(x));
    return y;
}
__device__ __forceinline__ float rnd32(float x) { return __uint_as_float(f2tf32(x)); }

__device__ __forceinline__ void cpasync16(void* dst, const void* src) {
    uint32_t d = (uint32_t)__cvta_generic_to_shared(dst);
    asm volatile("cp.async.cg.shared.global [%0], [%1], 16;" :: "r"(d), "l"(src));
}
#define CP_COMMIT() asm volatile("cp.async.commit_group;" ::: "memory")
#define CP_WAIT2()  asm volatile("cp.async.wait_group 2;" ::: "memory")

#define MMA_TF32(c, a0, a1, a2, a3, b0, b1) \
    asm volatile("mma.sync.aligned.m16n8k8.row.col.f32.tf32.tf32.f32 " \
        "{%0,%1,%2,%3}, {%4,%5,%6,%7}, {%8,%9}, {%0,%1,%2,%3};" \
        : "+f"((c)[0]), "+f"((c)[1]), "+f"((c)[2]), "+f"((c)[3]) \
        : "r"(a0), "r"(a1), "r"(a2), "r"(a3), "r"(b0), "r"(b1))

// ===========================================================================
// round ALL weights to tf32 (single launch)
// ===========================================================================
__global__ void round_all(const float* __restrict__ s0, const float* __restrict__ s1,
                          const float* __restrict__ s2, const float* __restrict__ s3,
                          const float* __restrict__ s4, const float* __restrict__ s5,
                          const float* __restrict__ s6)
{
    const float* srcs[7] = {s0, s1, s2, s3, s4, s5, s6};
    const int sizes[7] = {131072, 262144, 262144, 131072, 65536, 262144, 262144};
    const int offs[7]  = {WT_QCUT, WT_L, WT_KV, WT_EFORE, WT_EBACK, WT_PROJ, WT_PROJE};
    int y = blockIdx.y;
    int i = blockIdx.x * 256 + threadIdx.x;
    if (i < sizes[y]) g_wt[offs[y] + i] = rnd32(srcs[y][i]);
}

// ===========================================================================
// tf32 mma.sync GEMM, 4-stage cp.async pipeline.
//   C[M,N] = A[M,K] @ W[K,N] + bias.  A and W tf32-pre-rounded.
//   EPI: 0=none 1=exact GELU 2=*mul ; RND: round output to tf32
//   NJ=8: 128x128 tile (warp 32x64); NJ=4: 128x64 tile (warp 32x32)
// ===========================================================================
#define AS_STRIDE 20
#define AS_STAGE  (128 * AS_STRIDE)

template <int EPI, int RND, int NJ>
__global__ void __launch_bounds__(256, 2) gemm_mma(
    const float* __restrict__ A, const float* __restrict__ W,
    const float* __restrict__ bias, const float* __restrict__ mul,
    float* __restrict__ C, int K, int N, int ldc, int ldm)
{
    constexpr int NT = NJ * 16;             // block N-tile
    constexpr int BS_STRIDE = NT + 8;
    constexpr int BS_STAGE = 16 * BS_STRIDE;

    extern __shared__ float smp[];
    float* As = smp;
    float* Bs = smp + 4 * AS_STAGE;
    float* sbias = Bs + 4 * BS_STAGE;

    const int tid = threadIdx.x;
    const int warp = tid >> 5, lane = tid & 31;
    const int wm = warp & 3, wn = warp >> 2;
    const int mbase = blockIdx.y * 128;
    const int nbase = blockIdx.x * NT;
    const int l4 = lane >> 2, lk = lane & 3;

    const int arow = tid >> 1, ac4 = (tid & 1) * 2;

    if (tid < NT) sbias[tid] = bias[nbase + tid];

    const int NK = K >> 4;

    auto issue_stage = [&](int kt, int s) {
        float* a_s = As + s * AS_STAGE;
        float* b_s = Bs + s * BS_STAGE;
        const float* ga = A + (size_t)(mbase + arow) * K + kt * 16;
        cpasync16(a_s + arow * AS_STRIDE + ac4 * 4,       ga + ac4 * 4);
        cpasync16(a_s + arow * AS_STRIDE + (ac4 + 1) * 4, ga + (ac4 + 1) * 4);
        const int brow = tid >> 4;
        const float* gb = W + (size_t)(kt * 16 + brow) * N + nbase;
        #pragma unroll
        for (int c = 0; c < NJ / 4; c++) {
            int chunk = (tid & 15) * (NJ / 4) + c;
            cpasync16(b_s + brow * BS_STRIDE + chunk * 4, gb + chunk * 4);
        }
        CP_COMMIT();
    };

    float c[2][NJ][4];
    #pragma unroll
    for (int i = 0; i < 2; i++)
        #pragma unroll
        for (int j = 0; j < NJ; j++)
            #pragma unroll
            for (int r = 0; r < 4; r++) c[i][j][r] = 0.f;

    issue_stage(0, 0); issue_stage(1, 1); issue_stage(2, 2);

    #pragma unroll 4
    for (int kt = 0; kt < NK; kt++) {
        const int s = kt & 3;
        CP_WAIT2();
        __syncthreads();
        if (kt + 3 < NK) issue_stage(kt + 3, (kt + 3) & 3);

        const float* a_s = As + s * AS_STAGE;
        const float* b_s = Bs + s * BS_STAGE;
        #pragma unroll
        for (int ks = 0; ks < 2; ks++) {
            const int k0 = ks * 8;
            uint32_t af[2][4];
            #pragma unroll
            for (int i = 0; i < 2; i++) {
                int m0 = wm * 32 + i * 16;
                af[i][0] = __float_as_uint(a_s[(m0 + l4) * AS_STRIDE + k0 + lk]);
                af[i][1] = __float_as_uint(a_s[(m0 + 8 + l4) * AS_STRIDE + k0 + lk]);
                af[i][2] = __float_as_uint(a_s[(m0 + l4) * AS_STRIDE + k0 + lk + 4]);
                af[i][3] = __float_as_uint(a_s[(m0 + 8 + l4) * AS_STRIDE + k0 + lk + 4]);
            }
            uint32_t bf[NJ][2];
            #pragma unroll
            for (int j = 0; j < NJ; j++) {
                int n0 = wn * (NJ * 8) + j * 8 + l4;
                bf[j][0] = __float_as_uint(b_s[(k0 + lk) * BS_STRIDE + n0]);
                bf[j][1] = __float_as_uint(b_s[(k0 + lk + 4) * BS_STRIDE + n0]);
            }
            #pragma unroll
            for (int i = 0; i < 2; i++)
                #pragma unroll
                for (int j = 0; j < NJ; j++)
                    MMA_TF32(c[i][j], af[i][0], af[i][1], af[i][2], af[i][3],
                             bf[j][0], bf[j][1]);
        }
    }

    // epilogue
    #pragma unroll
    for (int i = 0; i < 2; i++) {
        int row0 = mbase + wm * 32 + i * 16 + l4;
        #pragma unroll
        for (int j = 0; j < NJ; j++) {
            int colL = wn * (NJ * 8) + j * 8 + lk * 2;
            int col = nbase + colL;
            float v0 = c[i][j][0] + sbias[colL];
            float v1 = c[i][j][1] + sbias[colL + 1];
            float v2 = c[i][j][2] + sbias[colL];
            float v3 = c[i][j][3] + sbias[colL + 1];
            if (EPI == 1) {
                v0 = 0.5f * v0 * (1.0f + erff(v0 * 0.70710678118654752f));
                v1 = 0.5f * v1 * (1.0f + erff(v1 * 0.70710678118654752f));
                v2 = 0.5f * v2 * (1.0f + erff(v2 * 0.70710678118654752f));
                v3 = 0.5f * v3 * (1.0f + erff(v3 * 0.70710678118654752f));
            }
            if (EPI == 2) {
                float2 m0 = *(const float2*)(mul + (size_t)row0 * ldm + col);
                float2 m1 = *(const float2*)(mul + (size_t)(row0 + 8) * ldm + col);
                v0 *= m0.x; v1 *= m0.y; v2 *= m1.x; v3 *= m1.y;
            }
            if (RND) { v0 = rnd32(v0); v1 = rnd32(v1); v2 = rnd32(v2); v3 = rnd32(v3); }
            *(float2*)(C + (size_t)row0 * ldc + col)       = make_float2(v0, v1);
            *(float2*)(C + (size_t)(row0 + 8) * ldc + col) = make_float2(v2, v3);
        }
    }
}
#define SMEM_GEMM8 ((4 * AS_STAGE + 4 * 16 * 136 + 128) * 4)
#define SMEM_GEMM4 ((4 * AS_STAGE + 4 * 16 * 72 + 64) * 4)

// ===========================================================================
// LayerNorm: 2 pixels per 256-thread block (tf32-rounded output)
// ===========================================================================
__global__ void ln_kernel(const float* __restrict__ x, const float* __restrict__ xe,
                          const float* __restrict__ nw, const float* __restrict__ nb,
                          const float* __restrict__ ew, const float* __restrict__ eb)
{
    int tid = threadIdx.x;
    int sub = tid >> 7, t = tid & 127;
    int p = blockIdx.x * 2 + sub;
    bool sec = p >= BHW;
    int pix = sec ? p - BHW : p;
    const float* src = (sec ? xe : x) + (size_t)pix * Cc;
    float*       dst = (sec ? g_xen : g_xn) + (size_t)pix * Cc;
    const float* w = sec ? ew : nw;
    const float* bb = sec ? eb : nb;

    float4 v = *(const float4*)(src + t * 4);
    float s  = v.x + v.y + v.z + v.w;
    float ss = v.x*v.x + v.y*v.y + v.z*v.z + v.w*v.w;
    #pragma unroll
    for (int o = 16; o > 0; o >>= 1) {
        s  += __shfl_xor_sync(0xffffffffu, s,  o);
        ss += __shfl_xor_sync(0xffffffffu, ss, o);
    }
    __shared__ float sm[2][4], sm2[2][4];
    int wid = t >> 5;
    if ((t & 31) == 0) { sm[sub][wid] = s; sm2[sub][wid] = ss; }
    __syncthreads();
    s = sm[sub][0] + sm[sub][1] + sm[sub][2] + sm[sub][3];
    ss = sm2[sub][0] + sm2[sub][1] + sm2[sub][2] + sm2[sub][3];
    float mu = s * (1.0f / Cc);
    float var = ss * (1.0f / Cc) - mu * mu;
    float inv = rsqrtf(var + 1e-6f);
    float4 wv = *(const float4*)(w + t * 4);
    float4 bv = *(const float4*)(bb + t * 4);
    float4 o;
    o.x = rnd32((v.x - mu) * inv * wv.x + bv.x);
    o.y = rnd32((v.y - mu) * inv * wv.y + bv.y);
    o.z = rnd32((v.z - mu) * inv * wv.z + bv.z);
    o.w = rnd32((v.w - mu) * inv * wv.w + bv.w);
    *(float4*)(dst + t * 4) = o;
}

// ===========================================================================
// Pool + mproj
// ===========================================================================
__global__ void pool_kernel()
{
    int blk = blockIdx.x;
    int b = blk / 49, pp = blk % 49;
    int pi = pp / 7, pj = pp % 7;
    int c4 = threadIdx.x * 4;
    const float* src = (c4 < Cc) ? g_xn : g_xen;
    int cc = (c4 < Cc) ? c4 : c4 - Cc;
    float4 s = make_float4(0.f, 0.f, 0.f, 0.f);
    for (int ii = 0; ii < 8; ii++)
        for (int jj = 0; jj < 8; jj++) {
            int pix = b * HW + (pi * 8 + ii) * Ww + (pj * 8 + jj);
            float4 v = *(const float4*)(src + (size_t)pix * Cc + cc);
            s.x += v.x; s.y += v.y; s.z += v.z; s.w += v.w;
        }
    const float inv = 1.0f / 64.0f;
    *(float4*)(g_pool + (size_t)blk * 1024 + c4) =
        make_float4(s.x * inv, s.y * inv, s.z * inv, s.w * inv);
}

__global__ void mproj_kernel(const float* __restrict__ sw, const float* __restrict__ sb)
{
    __shared__ float ps[8 * 1024];
    int r0 = blockIdx.x * 8, tid = threadIdx.x;
    for (int i = tid * 4; i < 8 * 1024; i += 1024)
        *(float4*)&ps[i] = *(const float4*)(g_pool + (size_t)r0 * 1024 + i);
    __syncthreads();
    float acc[8];
    float bias = sb[tid];
    #pragma unroll
    for (int r = 0; r < 8; r++) acc[r] = bias;
    for (int i = 0; i < 1024; i++) {
        float w = sw[(size_t)i * 256 + tid];
        #pragma unroll
        for (int r = 0; r < 8; r++) acc[r] += ps[r * 1024 + i] * w;
    }
    #pragma unroll
    for (int r = 0; r < 8; r++)
        g_m[(size_t)(r0 + r) * 256 + tid] = acc[r];
}

// ===========================================================================
// Fused flash attention (unchanged from round 4)
// ===========================================================================
#define ATT_MS    0
#define ATT_KT    1568
#define ATT_VT    (1568 + 3696)
#define ATT_SB    (1568 + 3696 + 3696)
#define ATT_QMAX  (ATT_SB + 5488)
#define ATT_QCORR (ATT_QMAX + 49)
#define SMEM_ATT  ((ATT_QCORR + 49) * 4)

__global__ void __launch_bounds__(256) attn_fused()
{
    extern __shared__ float sm[];
    float* ms    = sm + ATT_MS;
    float* ktile = sm + ATT_KT;
    float* vtile = sm + ATT_VT;
    float* sb    = sm + ATT_SB;
    float* qmax  = sm + ATT_QMAX;
    float* qcorr = sm + ATT_QCORR;

    int bn = blockIdx.x, cp = blockIdx.y;
    int b = bn >> 3, nh = bn & 7;
    int tid = threadIdx.x;
    int d = tid & 31, qg = tid >> 5;
    int kk = tid % 112, half = tid / 112;
    int q0 = half * 25, q1 = half ? 49 : 25;

    for (int i = tid; i < 49 * 32; i += 256)
        ms[i] = g_m[(size_t)(b * 49 + i / 32) * 256 + nh * 32 + (i & 31)]
                * 0.17677669529663689f;

    float rm = -3.4e38f, rs = 0.f;
    float acc[7] = {0.f, 0.f, 0.f, 0.f, 0.f, 0.f, 0.f};
    int hw0 = cp * 784;

    for (int st = 0; st < 7; st++) {
        __syncthreads();
        int base = b * HW + hw0 + st * 112;
        for (int u = tid; u < 112 * 8; u += 256) {
            int r = u >> 3, c = u & 7;
            const float* gp = g_kv + (size_t)(base + r) * Cc + nh * 32 + c * 4;
            float4 kv4 = *(const float4*)gp;
            float* dk = &ktile[r * 33 + c * 4];
            dk[0] = kv4.x; dk[1] = kv4.y; dk[2] = kv4.z; dk[3] = kv4.w;
            float4 vv4 = *(const float4*)(gp + C2);
            float* dv = &vtile[r * 33 + c * 4];
            dv[0] = vv4.x; dv[1] = vv4.y; dv[2] = vv4.z; dv[3] = vv4.w;
        }
        __syncthreads();
        if (tid < 224) {
            float kr[32];
            #pragma unroll
            for (int j = 0; j < 32; j++) kr[j] = ktile[kk * 33 + j];
            for (int q = q0; q < q1; q++) {
                float s = 0.f;
                #pragma unroll
                for (int j = 0; j < 32; j++) s += ms[q * 32 + j] * kr[j];
                sb[q * 112 + kk] = s;
            }
        }
        __syncthreads();
        if (tid < 49) {
            float m = rm;
            #pragma unroll 4
            for (int i = 0; i < 112; i++) m = fmaxf(m, sb[tid * 112 + i]);
            float corr = __expf(rm - m);
            qmax[tid] = m; qcorr[tid] = corr;
            rm = m; rs *= corr;
        }
        __syncthreads();
        if (tid < 224) {
            for (int q = q0; q < q1; q++)
                sb[q * 112 + kk] = __expf(sb[q * 112 + kk] - qmax[q]);
        }
        __syncthreads();
        if (qg < 7) {
            #pragma unroll
            for (int j = 0; j < 7; j++) {
                int q = qg * 7 + j;
                float t = 0.f;
                #pragma unroll 4
                for (int i = 0; i < 112; i++) t += sb[q * 112 + i] * vtile[i * 33 + d];
                acc[j] = acc[j] * qcorr[q] + t;
            }
        }
        if (tid < 49) {
            float s = 0.f;
            #pragma unroll 4
            for (int i = 0; i < 112; i++) s += sb[tid * 112 + i];
            rs += s;
        }
    }

    if (qg < 7) {
        #pragma unroll
        for (int j = 0; j < 7; j++)
            g_a49p[((size_t)(cp * 64 + bn) * 49 + qg * 7 + j) * 32 + d] = acc[j];
    }
    if (tid < 49) {
        g_mpart[(cp * 64 + bn) * 49 + tid] = rm;
        g_spart[(cp * 64 + bn) * 49 + tid] = rs;
    }
}

__global__ void attn_merge()
{
    __shared__ float w[4][49];
    int bn = blockIdx.x, tid = threadIdx.x;
    if (tid < 49) {
        float m[4], sgm[4];
        #pragma unroll
        for (int c = 0; c < 4; c++) {
            m[c]  = g_mpart[(c * 64 + bn) * 49 + tid];
            sgm[c] = g_spart[(c * 64 + bn) * 49 + tid];
        }
        float M = fmaxf(fmaxf(m[0], m[1]), fmaxf(m[2], m[3]));
        float e[4], D = 0.f;
        #pragma unroll
        for (int c = 0; c < 4; c++) { e[c] = __expf(m[c] - M); D += sgm[c] * e[c]; }
        float inv = 1.0f / D;
        #pragma unroll
        for (int c = 0; c < 4; c++) w[c][tid] = e[c] * inv;
    }
    __syncthreads();
    for (int u = tid; u < 49 * 32; u += 256) {
        int q = u >> 5, dd = u & 31;
        float v = 0.f;
        #pragma unroll
        for (int c = 0; c < 4; c++)
            v += g_a49p[((size_t)(c * 64 + bn) * 49 + q) * 32 + dd] * w[c][q];
        g_a49[((size_t)bn * 49 + q) * 32 + dd] = v;
    }
}

// ===========================================================================
// Bilinear 7->56 upsample, 8 pixels/block -> xcat[:, 0:256]
// ===========================================================================
__global__ void upsample_kernel()
{
    int c = threadIdx.x;
    int nh = c >> 5, dd = c & 31;
    #pragma unroll
    for (int k = 0; k < 8; k++) {
        int p = blockIdx.x * 8 + k;
        int b = p / HW, rem = p % HW;
        int y = rem / Ww, x = rem % Ww;
        int bn = b * NHh + nh;

        float sy = (y + 0.5f) * 0.125f - 0.5f;
        float sx = (x + 0.5f) * 0.125f - 0.5f;
        float fy = floorf(sy), fx = floorf(sx);
        float wy = sy - fy, wx = sx - fx;
        int y0 = max(0, min(6, (int)fy)), y1 = max(0, min(6, (int)fy + 1));
        int x0 = max(0, min(6, (int)fx)), x1 = max(0, min(6, (int)fx + 1));

        const float* A = g_a49 + (size_t)bn * 49 * 32 + dd;
        float s00 = A[(y0 * 7 + x0) * 32];
        float s01 = A[(y0 * 7 + x1) * 32];
        float s10 = A[(y1 * 7 + x0) * 32];
        float s11 = A[(y1 * 7 + x1) * 32];
        float v = (1.f - wy) * ((1.f - wx) * s00 + wx * s01)
                +        wy  * ((1.f - wx) * s10 + wx * s11);
        g_xcat[(size_t)p * Cc + c] = rnd32(v);
    }
}

// ===========================================================================
// Depthwise 7x7 conv, register row-sliding (98 LDS/thread instead of 392)
// ===========================================================================
__global__ void dwconv2(const float* __restrict__ wgt, const float* __restrict__ cb)
{
    __shared__ float tile[196 * 32];
    int sbk = blockIdx.x;
    int b = sbk / 49, t49 = sbk % 49;
    int ty0 = (t49 / 7) * 8, tx0 = (t49 % 7) * 8;
    int cg = blockIdx.y;
    int tid = threadIdx.x;
    int cl = tid & 31, pxg = tid >> 5;    // pxg = output row within tile
    int ch = cg * 32 + cl;

    for (int u = tid; u < 196 * 8; u += 256) {
        int px = u >> 3, c4 = u & 7;
        int iy = ty0 + px / 14 - 3;
        int ix = tx0 + px % 14 - 3;
        float4 v = make_float4(0.f, 0.f, 0.f, 0.f);
        if (iy >= 0 && iy < Hh && ix >= 0 && ix < Ww)
            v = *(const float4*)(g_e1 + ((size_t)(b * HW) + iy * Ww + ix) * C2 + cg * 32 + c4 * 4);
        *(float4*)&tile[px * 32 + c4 * 4] = v;
    }
    __syncthreads();

    float wr[49];
    #pragma unroll
    for (int i = 0; i < 49; i++) wr[i] = wgt[ch * 49 + i];
    float bias = cb[ch];

    float acc[8];
    #pragma unroll
    for (int ox = 0; ox < 8; ox++) acc[ox] = bias;

    #pragma unroll
    for (int ky = 0; ky < 7; ky++) {
        float row[14];
        #pragma unroll
        for (int i = 0; i < 14; i++)
            row[i] = tile[((pxg + ky) * 14 + i) * 32 + cl];
        #pragma unroll
        for (int kx = 0; kx < 7; kx++) {
            float w = wr[ky * 7 + kx];
            #pragma unroll
            for (int ox = 0; ox < 8; ox++)
                acc[ox] += row[ox + kx] * w;
        }
    }
    #pragma unroll
    for (int ox = 0; ox < 8; ox++)
        g_e2[((size_t)(b * HW) + (ty0 + pxg) * Ww + tx0 + ox) * C2 + ch] = rnd32(acc[ox]);
}

// ===========================================================================
// Launch
// ===========================================================================
extern "C" void kernel_launch(void* const* d_in, const int* in_sizes, int n_in,
                              void* d_out, int out_size)
{
    const float* x       = (const float*)d_in[0];
    const float* x_e     = (const float*)d_in[1];
    const float* norm_w  = (const float*)d_in[2];
    const float* norm_b  = (const float*)d_in[3];
    const float* norme_w = (const float*)d_in[4];
    const float* norme_b = (const float*)d_in[5];
    const float* qcut_w  = (const float*)d_in[6];
    const float* qcut_b  = (const float*)d_in[7];
    const float* l_w     = (const float*)d_in[8];
    const float* l_b     = (const float*)d_in[9];
    const float* kv_w    = (const float*)d_in[10];
    const float* kv_b    = (const float*)d_in[11];
    const float* sc_w    = (const float*)d_in[12];
    const float* sc_b    = (const float*)d_in[13];
    const float* efore_w = (const float*)d_in[14];
    const float* efore_b = (const float*)d_in[15];
    const float* econv_w = (const float*)d_in[16];
    const float* econv_b = (const float*)d_in[17];
    const float* eback_w = (const float*)d_in[18];
    const float* eback_b = (const float*)d_in[19];
    const float* proj_w  = (const float*)d_in[20];
    const float* proj_b  = (const float*)d_in[21];
    const float* proje_w = (const float*)d_in[22];
    const float* proje_b = (const float*)d_in[23];
    float* out = (float*)d_out;

    float *xn, *xen, *bfeat, *kv, *xcat, *cut, *e1, *e2, *wt;
    cudaGetSymbolAddress((void**)&xn,    g_xn);
    cudaGetSymbolAddress((void**)&xen,   g_xen);
    cudaGetSymbolAddress((void**)&bfeat, g_bfeat);
    cudaGetSymbolAddress((void**)&kv,    g_kv);
    cudaGetSymbolAddress((void**)&xcat,  g_xcat);
    cudaGetSymbolAddress((void**)&cut,   g_cut);
    cudaGetSymbolAddress((void**)&e1,    g_e1);
    cudaGetSymbolAddress((void**)&e2,    g_e2);
    cudaGetSymbolAddress((void**)&wt,    g_wt);

    cudaFuncSetAttribute((const void*)gemm_mma<0, 0, 8>,
                         cudaFuncAttributeMaxDynamicSharedMemorySize, SMEM_GEMM8);
    cudaFuncSetAttribute((const void*)gemm_mma<1, 1, 8>,
                         cudaFuncAttributeMaxDynamicSharedMemorySize, SMEM_GEMM8);
    cudaFuncSetAttribute((const void*)gemm_mma<0, 0, 4>,
                         cudaFuncAttributeMaxDynamicSharedMemorySize, SMEM_GEMM4);
    cudaFuncSetAttribute((const void*)gemm_mma<2, 1, 4>,
                         cudaFuncAttributeMaxDynamicSharedMemorySize, SMEM_GEMM4);
    cudaFuncSetAttribute((const void*)attn_fused,
                         cudaFuncAttributeMaxDynamicSharedMemorySize, SMEM_ATT);

    // 0. round all weights (one launch)
    round_all<<<dim3(1024, 7), 256>>>(qcut_w, l_w, kv_w, efore_w, eback_w, proj_w, proje_w);

    // 1. LayerNorms (2 pixels/block)
    ln_kernel<<<BHW, 256>>>(x, x_e, norm_w, norm_b, norme_w, norme_b);

    // 2-3. pooled queries
    pool_kernel<<<Bn * 49, 256>>>();
    mproj_kernel<<<49, 256>>>(sc_w, sc_b);

    // 4-6. main GEMMs
    gemm_mma<0, 0, 4><<<dim3(4, 196), 256, SMEM_GEMM4>>>(xn, wt + WT_QCUT, qcut_b, nullptr,
                                                         cut, 512, 256, 256, 0);
    gemm_mma<1, 1, 8><<<dim3(4, 196), 256, SMEM_GEMM8>>>(xn, wt + WT_L, l_b, nullptr,
                                                         bfeat, 512, 512, 512, 0);
    gemm_mma<0, 0, 8><<<dim3(4, 196), 256, SMEM_GEMM8>>>(bfeat, wt + WT_KV, kv_b, nullptr,
                                                         kv, 512, 512, 512, 0);

    // 7-8. fused attention + merge
    attn_fused<<<dim3(64, 4), 256, SMEM_ATT>>>();
    attn_merge<<<64, 256>>>();

    // 9. upsample -> xcat[:, 0:256]
    upsample_kernel<<<BHW / 8, 256>>>();

    // 10-12. gating branch
    gemm_mma<0, 0, 4><<<dim3(4, 196), 256, SMEM_GEMM4>>>(xen, wt + WT_EFORE, efore_b, nullptr,
                                                         e1, 512, 256, 256, 0);
    dwconv2<<<dim3(392, 8), 256>>>(econv_w, econv_b);
    gemm_mma<2, 1, 4><<<dim3(4, 196), 256, SMEM_GEMM4>>>(e2, wt + WT_EBACK, eback_b, cut,
                                                         xcat + 256, 256, 256, 512, 256);

    // 13-14. output projections
    gemm_mma<0, 0, 8><<<dim3(4, 196), 256, SMEM_GEMM8>>>(xcat, wt + WT_PROJ, proj_b, nullptr,
                                                         out, 512, 512, 512, 0);
    gemm_mma<0, 0, 8><<<dim3(4, 196), 256, SMEM_GEMM8>>>(xcat, wt + WT_PROJE, proje_b, nullptr,
                                                         out + (size_t)BHW * Cc, 512, 512, 512, 0);
}